// round 1
// baseline (speedup 1.0000x reference)
#include <cuda_runtime.h>

#define RR 256
#define CC 32
#define SS 8
#define HH 32

__global__ __launch_bounds__(256) void decoders_kernel(
    const float* __restrict__ p,
    const float* __restrict__ boundaries,
    const float* __restrict__ pxy, const float* __restrict__ pxz, const float* __restrict__ pyz,
    const float* __restrict__ cxy, const float* __restrict__ cxz, const float* __restrict__ cyz,
    const float* __restrict__ w0, const float* __restrict__ b0,
    const float* __restrict__ w1, const float* __restrict__ b1,
    const float* __restrict__ w_out, const float* __restrict__ b_out,
    const float* __restrict__ cw0, const float* __restrict__ cb0,
    const float* __restrict__ cw1, const float* __restrict__ cb1,
    const float* __restrict__ cw_out, const float* __restrict__ cb_out,
    float* __restrict__ out, int n)
{
    __shared__ float sw0[CC*HH], sw1[HH*HH], scw0[CC*HH], scw1[HH*HH];
    __shared__ float sb0[HH], sb1[HH], scb0[HH], scb1[HH];
    __shared__ float swout[HH], scwout[HH*3];
    __shared__ float sbnd[SS*6];
    __shared__ float sbo, scbo[3];

    const int tid = threadIdx.x;
    for (int i = tid; i < CC*HH; i += blockDim.x) {
        sw0[i]  = w0[i];  sw1[i]  = w1[i];
        scw0[i] = cw0[i]; scw1[i] = cw1[i];
    }
    if (tid < HH) {
        sb0[tid] = b0[tid]; sb1[tid] = b1[tid];
        scb0[tid] = cb0[tid]; scb1[tid] = cb1[tid];
        swout[tid] = w_out[tid];
    }
    if (tid < HH*3) scwout[tid] = cw_out[tid];
    if (tid < SS*6) sbnd[tid] = boundaries[tid];   // [s][0=lo,1=hi][3]
    if (tid == 0) sbo = b_out[0];
    if (tid < 3) scbo[tid] = cb_out[tid];
    __syncthreads();

    int idx = blockIdx.x * blockDim.x + tid;
    if (idx >= n) return;

    const float px = p[idx*3 + 0];
    const float py = p[idx*3 + 1];
    const float pz = p[idx*3 + 2];

    // first segment whose open box contains p (argmax of bool = first true)
    int s = 0; bool valid = false;
    #pragma unroll
    for (int k = SS - 1; k >= 0; k--) {
        const float lx = sbnd[k*6+0], ly = sbnd[k*6+1], lz = sbnd[k*6+2];
        const float hx = sbnd[k*6+3], hy = sbnd[k*6+4], hz = sbnd[k*6+5];
        const bool in = (px > lx) & (px < hx) & (py > ly) & (py < hy) & (pz > lz) & (pz < hz);
        if (in) { s = k; valid = true; }
    }

    const float bx0 = sbnd[s*6+0], by0 = sbnd[s*6+1], bz0 = sbnd[s*6+2];
    const float bx1 = sbnd[s*6+3], by1 = sbnd[s*6+4], bz1 = sbnd[s*6+5];
    const float pnx = (px - bx0) / (bx1 - bx0) * 2.0f - 1.0f;
    const float pny = (py - by0) / (by1 - by0) * 2.0f - 1.0f;
    const float pnz = (pz - bz0) / (bz1 - bz0) * 2.0f - 1.0f;

    // bilerp coords for the three plane pairs: xy:(x,y)  xz:(x,z)  yz:(y,z)
    struct UV { int x0, y0; float wx, wy; };
    UV uv[3];
    {
        const float us[3] = { pnx, pnx, pny };
        const float vs[3] = { pny, pnz, pnz };
        #pragma unroll
        for (int t = 0; t < 3; t++) {
            float x = (us[t] + 1.0f) * 0.5f * (float)(RR - 1);
            float y = (vs[t] + 1.0f) * 0.5f * (float)(RR - 1);
            float xf = fminf(fmaxf(floorf(x), 0.0f), (float)(RR - 2));
            float yf = fminf(fmaxf(floorf(y), 0.0f), (float)(RR - 2));
            uv[t].x0 = (int)xf; uv[t].y0 = (int)yf;
            uv[t].wx = x - xf;  uv[t].wy = y - yf;
        }
    }

    const float m = valid ? 1.0f : 0.0f;
    const float* planesA[3] = { pxy, pxz, pyz };
    const float* planesB[3] = { cxy, cxz, cyz };

    float feat[CC];

    // ---------- SDF branch ----------
    #pragma unroll
    for (int c = 0; c < CC; c++) feat[c] = 0.0f;
    #pragma unroll
    for (int t = 0; t < 3; t++) {
        const float wx = uv[t].wx, wy = uv[t].wy;
        const float w00 = (1.0f - wx) * (1.0f - wy);
        const float w01 = wx * (1.0f - wy);
        const float w10 = (1.0f - wx) * wy;
        const float w11 = wx * wy;
        const float* base = planesA[t] + (size_t)(((s * RR + uv[t].y0) * RR + uv[t].x0)) * CC;
        const float4* b00 = (const float4*)base;
        const float4* b01 = (const float4*)(base + CC);
        const float4* b10 = (const float4*)(base + RR * CC);
        const float4* b11 = (const float4*)(base + RR * CC + CC);
        #pragma unroll
        for (int c = 0; c < CC/4; c++) {
            float4 f00 = b00[c], f01 = b01[c], f10 = b10[c], f11 = b11[c];
            feat[c*4+0] += w00*f00.x + w01*f01.x + w10*f10.x + w11*f11.x;
            feat[c*4+1] += w00*f00.y + w01*f01.y + w10*f10.y + w11*f11.y;
            feat[c*4+2] += w00*f00.z + w01*f01.z + w10*f10.z + w11*f11.z;
            feat[c*4+3] += w00*f00.w + w01*f01.w + w10*f10.w + w11*f11.w;
        }
    }
    #pragma unroll
    for (int c = 0; c < CC; c++) feat[c] *= m;

    float h[HH];
    #pragma unroll
    for (int j = 0; j < HH; j++) h[j] = sb0[j];
    #pragma unroll
    for (int i = 0; i < CC; i++) {
        const float f = feat[i];
        #pragma unroll
        for (int j = 0; j < HH; j++) h[j] += f * sw0[i*HH + j];
    }
    #pragma unroll
    for (int j = 0; j < HH; j++) h[j] = fmaxf(h[j], 0.0f);

    float h2[HH];
    #pragma unroll
    for (int j = 0; j < HH; j++) h2[j] = sb1[j];
    #pragma unroll
    for (int i = 0; i < HH; i++) {
        const float f = h[i];
        #pragma unroll
        for (int j = 0; j < HH; j++) h2[j] += f * sw1[i*HH + j];
    }
    float sdf_acc = sbo;
    #pragma unroll
    for (int j = 0; j < HH; j++) sdf_acc += fmaxf(h2[j], 0.0f) * swout[j];
    const float sdf = tanhf(sdf_acc);

    // ---------- Color branch ----------
    #pragma unroll
    for (int c = 0; c < CC; c++) feat[c] = 0.0f;
    #pragma unroll
    for (int t = 0; t < 3; t++) {
        const float wx = uv[t].wx, wy = uv[t].wy;
        const float w00 = (1.0f - wx) * (1.0f - wy);
        const float w01 = wx * (1.0f - wy);
        const float w10 = (1.0f - wx) * wy;
        const float w11 = wx * wy;
        const float* base = planesB[t] + (size_t)(((s * RR + uv[t].y0) * RR + uv[t].x0)) * CC;
        const float4* b00 = (const float4*)base;
        const float4* b01 = (const float4*)(base + CC);
        const float4* b10 = (const float4*)(base + RR * CC);
        const float4* b11 = (const float4*)(base + RR * CC + CC);
        #pragma unroll
        for (int c = 0; c < CC/4; c++) {
            float4 f00 = b00[c], f01 = b01[c], f10 = b10[c], f11 = b11[c];
            feat[c*4+0] += w00*f00.x + w01*f01.x + w10*f10.x + w11*f11.x;
            feat[c*4+1] += w00*f00.y + w01*f01.y + w10*f10.y + w11*f11.y;
            feat[c*4+2] += w00*f00.z + w01*f01.z + w10*f10.z + w11*f11.z;
            feat[c*4+3] += w00*f00.w + w01*f01.w + w10*f10.w + w11*f11.w;
        }
    }
    #pragma unroll
    for (int c = 0; c < CC; c++) feat[c] *= m;

    #pragma unroll
    for (int j = 0; j < HH; j++) h[j] = scb0[j];
    #pragma unroll
    for (int i = 0; i < CC; i++) {
        const float f = feat[i];
        #pragma unroll
        for (int j = 0; j < HH; j++) h[j] += f * scw0[i*HH + j];
    }
    #pragma unroll
    for (int j = 0; j < HH; j++) h[j] = fmaxf(h[j], 0.0f);

    #pragma unroll
    for (int j = 0; j < HH; j++) h2[j] = scb1[j];
    #pragma unroll
    for (int i = 0; i < HH; i++) {
        const float f = h[i];
        #pragma unroll
        for (int j = 0; j < HH; j++) h2[j] += f * scw1[i*HH + j];
    }
    float r_acc = scbo[0], g_acc = scbo[1], b_acc = scbo[2];
    #pragma unroll
    for (int j = 0; j < HH; j++) {
        const float hv = fmaxf(h2[j], 0.0f);
        r_acc += hv * scwout[j*3 + 0];
        g_acc += hv * scwout[j*3 + 1];
        b_acc += hv * scwout[j*3 + 2];
    }
    const float rr = 1.0f / (1.0f + expf(-r_acc));
    const float gg = 1.0f / (1.0f + expf(-g_acc));
    const float bb = 1.0f / (1.0f + expf(-b_acc));

    float4 o; o.x = rr; o.y = gg; o.z = bb; o.w = sdf;
    ((float4*)out)[idx] = o;
}

extern "C" void kernel_launch(void* const* d_in, const int* in_sizes, int n_in,
                              void* d_out, int out_size) {
    const float* p          = (const float*)d_in[0];
    const float* boundaries = (const float*)d_in[1];
    const float* pxy        = (const float*)d_in[2];
    const float* pxz        = (const float*)d_in[3];
    const float* pyz        = (const float*)d_in[4];
    const float* cxy        = (const float*)d_in[5];
    const float* cxz        = (const float*)d_in[6];
    const float* cyz        = (const float*)d_in[7];
    const float* w0         = (const float*)d_in[8];
    const float* b0         = (const float*)d_in[9];
    const float* w1         = (const float*)d_in[10];
    const float* b1         = (const float*)d_in[11];
    const float* w_out      = (const float*)d_in[12];
    const float* b_out      = (const float*)d_in[13];
    const float* cw0        = (const float*)d_in[14];
    const float* cb0        = (const float*)d_in[15];
    const float* cw1        = (const float*)d_in[16];
    const float* cb1        = (const float*)d_in[17];
    const float* cw_out     = (const float*)d_in[18];
    const float* cb_out     = (const float*)d_in[19];

    const int n = in_sizes[0] / 3;
    float* out = (float*)d_out;

    const int threads = 256;
    const int blocks = (n + threads - 1) / threads;
    decoders_kernel<<<blocks, threads>>>(
        p, boundaries, pxy, pxz, pyz, cxy, cxz, cyz,
        w0, b0, w1, b1, w_out, b_out,
        cw0, cb0, cw1, cb1, cw_out, cb_out,
        out, n);
}